// round 6
// baseline (speedup 1.0000x reference)
#include <cuda_runtime.h>
#include <math.h>

typedef unsigned long long ull;

#define B 8
#define L 4096
#define H 16
#define E 64
#define BH (B*H)
#define EPSF 1e-6f
#define NEG_CLAMP -20.0f

#define P1_SPLIT 8
#define P1_CHUNK (L/P1_SPLIT)   // 512 tokens per block
#define TILE1 32
#define NT1 (P1_CHUNK/TILE1)    // 16 tiles

#define P2_SPLIT 8
#define P2_CHUNK (L/P2_SPLIT)
#define TILE2 32

// Per-split partial accumulators (plain stores, no atomics, no zero kernel).
__device__ float g_kv_part[P1_SPLIT][BH][E*E];   // 16 MB
__device__ float g_ksum_part[P1_SPLIT][BH][E];   // 256 KB

__device__ __forceinline__ float soft_logit_exp(float x, float inv_temp) {
    float v = (x < 0.0f) ? NEG_CLAMP : x;
    return __expf(v * inv_temp);
}

// packed-f32x2 helpers
#define FFMA2(d,a,b,c) asm("fma.rn.f32x2 %0, %1, %2, %3;" : "=l"(d) : "l"(a), "l"(b), "l"(c))
__device__ __forceinline__ ull dup2(float x) {
    unsigned u = __float_as_uint(x);
    return (ull)u | ((ull)u << 32);
}
__device__ __forceinline__ float lo_f(ull u) { return __uint_as_float((unsigned)u); }
__device__ __forceinline__ float hi_f(ull u) { return __uint_as_float((unsigned)(u >> 32)); }

// ---------------------------------------------------------------------------
// Phase 1: kv_part[split][bh][d][e] = sum_{l in chunk} softmax(k)[l][d]*v[l][e]
// grid (BH, P1_SPLIT), 256 threads. Double-buffered global loads.
// ---------------------------------------------------------------------------
__global__ __launch_bounds__(256, 1)
void phase1_kernel(const float* __restrict__ keys,
                   const float* __restrict__ values,
                   const float* __restrict__ delta1) {
    __shared__ __align__(16) float2 k_dup[TILE1][E];   // 16 KB {k,k}
    __shared__ __align__(16) float  v_sm[TILE1][E];    // 8 KB
    __shared__ float  ksum_sm[E];

    const int bh    = blockIdx.x;
    const int split = blockIdx.y;
    const int b = bh >> 4;
    const int h = bh & 15;
    const int tid   = threadIdx.x;
    const int lane8 = tid & 7;
    const int tok8  = tid >> 3;
    const int lane16 = tid & 15;
    const int tokg   = tid >> 4;
    const int d0 = tokg * 4;
    const int e0 = lane16 * 4;

    const float inv_temp = 1.0f / log1pf(__expf(delta1[0]));

    if (tid < E) ksum_sm[tid] = 0.0f;

    ull acc[4][2];
    #pragma unroll
    for (int i = 0; i < 4; i++) { acc[i][0] = 0ull; acc[i][1] = 0ull; }
    float ksl[8];
    #pragma unroll
    for (int j = 0; j < 8; j++) ksl[j] = 0.0f;

    const int l0 = split * P1_CHUNK;
    // base global offset for this thread's token row (advance by TILE1*H*E per tile)
    size_t off = ((size_t)(b * L + l0 + tok8) * H + h) * E + (size_t)(lane8 * 8);
    const size_t step = (size_t)TILE1 * H * E;

    // prologue: load tile 0
    float4 ka4 = *(const float4*)(keys + off);
    float4 kb4 = *(const float4*)(keys + off + 4);
    float4 va4 = *(const float4*)(values + off);
    float4 vb4 = *(const float4*)(values + off + 4);

    for (int tile = 0; tile < NT1; tile++) {
        // ---- softmax(k) from registers ----
        float x[8];
        x[0] = soft_logit_exp(ka4.x, inv_temp);
        x[1] = soft_logit_exp(ka4.y, inv_temp);
        x[2] = soft_logit_exp(ka4.z, inv_temp);
        x[3] = soft_logit_exp(ka4.w, inv_temp);
        x[4] = soft_logit_exp(kb4.x, inv_temp);
        x[5] = soft_logit_exp(kb4.y, inv_temp);
        x[6] = soft_logit_exp(kb4.z, inv_temp);
        x[7] = soft_logit_exp(kb4.w, inv_temp);
        float s = ((x[0]+x[1]) + (x[2]+x[3])) + ((x[4]+x[5]) + (x[6]+x[7]));
        #pragma unroll
        for (int m = 4; m >= 1; m >>= 1)
            s += __shfl_xor_sync(0xffffffffu, s, m, 8);
        float inv = 1.0f / s;
        #pragma unroll
        for (int j = 0; j < 8; j++) { x[j] *= inv; ksl[j] += x[j]; }

        ulonglong2* kd = (ulonglong2*)&k_dup[tok8][lane8 * 8];
        kd[0] = make_ulonglong2(dup2(x[0]), dup2(x[1]));
        kd[1] = make_ulonglong2(dup2(x[2]), dup2(x[3]));
        kd[2] = make_ulonglong2(dup2(x[4]), dup2(x[5]));
        kd[3] = make_ulonglong2(dup2(x[6]), dup2(x[7]));
        *(float4*)&v_sm[tok8][lane8 * 8]     = va4;
        *(float4*)&v_sm[tok8][lane8 * 8 + 4] = vb4;
        __syncthreads();

        // ---- prefetch next tile (latency hidden under FMA loop) ----
        if (tile + 1 < NT1) {
            off += step;
            ka4 = *(const float4*)(keys + off);
            kb4 = *(const float4*)(keys + off + 4);
            va4 = *(const float4*)(values + off);
            vb4 = *(const float4*)(values + off + 4);
        }

        // ---- accumulate 4x4 tile (as 4x2 f32x2) over 32 tokens ----
        #pragma unroll 4
        for (int t = 0; t < TILE1; t++) {
            const ulonglong2 ka = *(const ulonglong2*)&k_dup[t][d0];
            const ulonglong2 kb = *(const ulonglong2*)&k_dup[t][d0 + 2];
            const ulonglong2 vv = *(const ulonglong2*)&v_sm[t][e0];
            FFMA2(acc[0][0], ka.x, vv.x, acc[0][0]);
            FFMA2(acc[0][1], ka.x, vv.y, acc[0][1]);
            FFMA2(acc[1][0], ka.y, vv.x, acc[1][0]);
            FFMA2(acc[1][1], ka.y, vv.y, acc[1][1]);
            FFMA2(acc[2][0], kb.x, vv.x, acc[2][0]);
            FFMA2(acc[2][1], kb.x, vv.y, acc[2][1]);
            FFMA2(acc[3][0], kb.y, vv.x, acc[3][0]);
            FFMA2(acc[3][1], kb.y, vv.y, acc[3][1]);
        }
        __syncthreads();
    }

    // ---- block-reduce ksum into smem, then plain store ----
    #pragma unroll
    for (int j = 0; j < 8; j++) {
        float v = ksl[j];
        v += __shfl_xor_sync(0xffffffffu, v, 8);
        v += __shfl_xor_sync(0xffffffffu, v, 16);
        if ((tid & 24) == 0) atomicAdd(&ksum_sm[lane8 * 8 + j], v);
    }
    __syncthreads();
    if (tid < E) g_ksum_part[split][bh][tid] = ksum_sm[tid];

    // ---- store kv partial tile (plain 128-bit stores, unique per block) ----
    float* kvp = g_kv_part[split][bh];
    #pragma unroll
    for (int i = 0; i < 4; i++) {
        ulonglong2 row = make_ulonglong2(acc[i][0], acc[i][1]);  // 4 floats e0..e0+3
        *(ulonglong2*)&kvp[(d0 + i) * E + e0] = row;
    }
}

// ---------------------------------------------------------------------------
// Phase 2: out = z_l * softmax(q) @ kv ; kv = sum of 8 partials (read here)
// grid (BH, P2_SPLIT), 256 threads.
// ---------------------------------------------------------------------------
__global__ __launch_bounds__(256, 1)
void phase2_kernel(const float* __restrict__ queries,
                   const float* __restrict__ delta1,
                   float* __restrict__ out) {
    __shared__ __align__(16) float  kv_sm[E][E];          // 16 KB
    __shared__ __align__(16) float2 q_dup[TILE2][E + 2];  // row = 528 B (16B-aligned)
    __shared__ float  ksum_sm[E];
    __shared__ float  z_sm[TILE2];

    const int bh    = blockIdx.x;
    const int split = blockIdx.y;
    const int b = bh >> 4;
    const int h = bh & 15;
    const int tid   = threadIdx.x;
    const int lane8 = tid & 7;
    const int tok8  = tid >> 3;
    const int lane16 = tid & 15;
    const int tp     = tid >> 4;
    const int d0 = lane16 * 4;

    const float inv_temp = 1.0f / log1pf(__expf(delta1[0]));

    {   // load kv (sum of 8 split partials) + ksum
        float4* dst = (float4*)&kv_sm[0][0];
        #pragma unroll
        for (int i = 0; i < E*E/4/256; i++) {
            int idx = tid + i * 256;
            float4 acc4 = make_float4(0.f, 0.f, 0.f, 0.f);
            #pragma unroll
            for (int sp = 0; sp < P1_SPLIT; sp++) {
                float4 p = *(const float4*)&g_kv_part[sp][bh][idx * 4];
                acc4.x += p.x; acc4.y += p.y; acc4.z += p.z; acc4.w += p.w;
            }
            dst[idx] = acc4;
        }
        if (tid < E) {
            float sv = 0.f;
            #pragma unroll
            for (int sp = 0; sp < P1_SPLIT; sp++) sv += g_ksum_part[sp][bh][tid];
            ksum_sm[tid] = sv;
        }
    }
    __syncthreads();

    const int l0 = split * P2_CHUNK;
    const int t0 = 2 * tp, t1 = 2 * tp + 1;

    for (int tile = 0; tile < P2_CHUNK / TILE2; tile++) {
        // ---- load + softmax(q) + z for 32 tokens ----
        const int l = l0 + tile * TILE2 + tok8;
        const size_t off = ((size_t)(b * L + l) * H + h) * E + (size_t)(lane8 * 8);
        float4 qa4 = *(const float4*)(queries + off);
        float4 qb4 = *(const float4*)(queries + off + 4);

        float x[8];
        x[0] = soft_logit_exp(qa4.x, inv_temp);
        x[1] = soft_logit_exp(qa4.y, inv_temp);
        x[2] = soft_logit_exp(qa4.z, inv_temp);
        x[3] = soft_logit_exp(qa4.w, inv_temp);
        x[4] = soft_logit_exp(qb4.x, inv_temp);
        x[5] = soft_logit_exp(qb4.y, inv_temp);
        x[6] = soft_logit_exp(qb4.z, inv_temp);
        x[7] = soft_logit_exp(qb4.w, inv_temp);
        float s = ((x[0]+x[1]) + (x[2]+x[3])) + ((x[4]+x[5]) + (x[6]+x[7]));
        #pragma unroll
        for (int m = 4; m >= 1; m >>= 1)
            s += __shfl_xor_sync(0xffffffffu, s, m, 8);
        float inv = 1.0f / s;
        #pragma unroll
        for (int j = 0; j < 8; j++) x[j] *= inv;

        float zd = 0.0f;
        #pragma unroll
        for (int j = 0; j < 8; j++) zd = fmaf(x[j], ksum_sm[lane8 * 8 + j], zd);
        #pragma unroll
        for (int m = 4; m >= 1; m >>= 1)
            zd += __shfl_xor_sync(0xffffffffu, zd, m, 8);
        if (lane8 == 0) z_sm[tok8] = 1.0f / (zd + EPSF);

        ulonglong2* qd = (ulonglong2*)&q_dup[tok8][lane8 * 8];
        qd[0] = make_ulonglong2(dup2(x[0]), dup2(x[1]));
        qd[1] = make_ulonglong2(dup2(x[2]), dup2(x[3]));
        qd[2] = make_ulonglong2(dup2(x[4]), dup2(x[5]));
        qd[3] = make_ulonglong2(dup2(x[6]), dup2(x[7]));
        __syncwarp();   // producers & consumers of these tokens share this warp

        // ---- GEMV: 2 tokens x 4 d per thread, f32x2 on d-pairs ----
        ull a0 = 0ull, a1 = 0ull, b0 = 0ull, b1 = 0ull;
        #pragma unroll 16
        for (int e = 0; e < E; e++) {
            const ull qa = *(const ull*)&q_dup[t0][e];
            const ull qb = *(const ull*)&q_dup[t1][e];
            const ulonglong2 kv2 = *(const ulonglong2*)&kv_sm[e][d0];
            FFMA2(a0, qa, kv2.x, a0);
            FFMA2(a1, qa, kv2.y, a1);
            FFMA2(b0, qb, kv2.x, b0);
            FFMA2(b1, qb, kv2.y, b1);
        }
        const float z0 = z_sm[t0];
        const float z1 = z_sm[t1];
        const size_t off0 = ((size_t)(b * L + l0 + tile * TILE2 + t0) * H + h) * E + (size_t)d0;
        const size_t off1 = off0 + (size_t)(H * E);
        *(float4*)(out + off0) = make_float4(lo_f(a0)*z0, hi_f(a0)*z0, lo_f(a1)*z0, hi_f(a1)*z0);
        *(float4*)(out + off1) = make_float4(lo_f(b0)*z1, hi_f(b0)*z1, lo_f(b1)*z1, hi_f(b1)*z1);
        __syncwarp();   // protect q_dup/z_sm reuse next tile
    }
}

extern "C" void kernel_launch(void* const* d_in, const int* in_sizes, int n_in,
                              void* d_out, int out_size) {
    const float* queries = (const float*)d_in[0];
    const float* keys    = (const float*)d_in[1];
    const float* values  = (const float*)d_in[2];
    const float* delta1  = (const float*)d_in[3];
    float* out = (float*)d_out;

    (void)in_sizes; (void)n_in; (void)out_size;

    phase1_kernel<<<dim3(BH, P1_SPLIT), 256>>>(keys, values, delta1);
    phase2_kernel<<<dim3(BH, P2_SPLIT), 256>>>(queries, delta1, out);
}

// round 10
// speedup vs baseline: 1.1116x; 1.1116x over previous
#include <cuda_runtime.h>
#include <math.h>

typedef unsigned long long ull;

#define B 8
#define L 4096
#define H 16
#define E 64
#define BH (B*H)
#define EPSF 1e-6f
#define NEG_CLAMP -20.0f

#define P1_SPLIT 8
#define P1_CHUNK (L/P1_SPLIT)   // 512 tokens per block
#define TILE1 32
#define NT1 (P1_CHUNK/TILE1)    // 16 tiles

#define P2_SPLIT 8
#define P2_CHUNK (L/P2_SPLIT)   // 512
#define TILE2 128               // tokens per tile (4 tiles per block)

// Phase-2 dynamic smem layout
#define SM_KV   0
#define SM_Q    (E*E*4)                 // 16384
#define SM_KSUM (SM_Q + TILE2*E*4)      // 16384+32768 = 49152
#define SM2_TOTAL (SM_KSUM + E*4)       // 49408

// Per-split partial accumulators (plain stores, no atomics, no zero kernel).
__device__ float g_kv_part[P1_SPLIT][BH][E*E];   // 16 MB
__device__ float g_ksum_part[P1_SPLIT][BH][E];   // 256 KB

__device__ __forceinline__ float soft_logit_exp(float x, float inv_temp) {
    float v = (x < 0.0f) ? NEG_CLAMP : x;
    return __expf(v * inv_temp);
}

// packed-f32x2 helpers
#define FFMA2(d,a,b,c) asm("fma.rn.f32x2 %0, %1, %2, %3;" : "=l"(d) : "l"(a), "l"(b), "l"(c))
__device__ __forceinline__ ull dup2(float x) {
    unsigned u = __float_as_uint(x);
    return (ull)u | ((ull)u << 32);
}
__device__ __forceinline__ float lo_f(ull u) { return __uint_as_float((unsigned)u); }
__device__ __forceinline__ float hi_f(ull u) { return __uint_as_float((unsigned)(u >> 32)); }

// ---------------------------------------------------------------------------
// Phase 1: kv_part[split][bh][d][e] = sum_{l in chunk} softmax(k)[l][d]*v[l][e]
// grid (BH, P1_SPLIT), 256 threads. Double-buffered global loads.
// ---------------------------------------------------------------------------
__global__ __launch_bounds__(256, 2)
void phase1_kernel(const float* __restrict__ keys,
                   const float* __restrict__ values,
                   const float* __restrict__ delta1) {
    __shared__ __align__(16) float2 k_dup[TILE1][E];   // 16 KB {k,k}
    __shared__ __align__(16) float  v_sm[TILE1][E];    // 8 KB
    __shared__ float  ksum_sm[E];

    const int bh    = blockIdx.x;
    const int split = blockIdx.y;
    const int b = bh >> 4;
    const int h = bh & 15;
    const int tid   = threadIdx.x;
    const int lane8 = tid & 7;
    const int tok8  = tid >> 3;
    const int lane16 = tid & 15;
    const int tokg   = tid >> 4;
    const int d0 = tokg * 4;
    const int e0 = lane16 * 4;

    const float inv_temp = 1.0f / log1pf(__expf(delta1[0]));

    if (tid < E) ksum_sm[tid] = 0.0f;

    ull acc[4][2];
    #pragma unroll
    for (int i = 0; i < 4; i++) { acc[i][0] = 0ull; acc[i][1] = 0ull; }
    float ksl[8];
    #pragma unroll
    for (int j = 0; j < 8; j++) ksl[j] = 0.0f;

    const int l0 = split * P1_CHUNK;
    size_t off = ((size_t)(b * L + l0 + tok8) * H + h) * E + (size_t)(lane8 * 8);
    const size_t step = (size_t)TILE1 * H * E;

    // prologue: load tile 0
    float4 ka4 = *(const float4*)(keys + off);
    float4 kb4 = *(const float4*)(keys + off + 4);
    float4 va4 = *(const float4*)(values + off);
    float4 vb4 = *(const float4*)(values + off + 4);

    for (int tile = 0; tile < NT1; tile++) {
        float x[8];
        x[0] = soft_logit_exp(ka4.x, inv_temp);
        x[1] = soft_logit_exp(ka4.y, inv_temp);
        x[2] = soft_logit_exp(ka4.z, inv_temp);
        x[3] = soft_logit_exp(ka4.w, inv_temp);
        x[4] = soft_logit_exp(kb4.x, inv_temp);
        x[5] = soft_logit_exp(kb4.y, inv_temp);
        x[6] = soft_logit_exp(kb4.z, inv_temp);
        x[7] = soft_logit_exp(kb4.w, inv_temp);
        float s = ((x[0]+x[1]) + (x[2]+x[3])) + ((x[4]+x[5]) + (x[6]+x[7]));
        #pragma unroll
        for (int m = 4; m >= 1; m >>= 1)
            s += __shfl_xor_sync(0xffffffffu, s, m, 8);
        float inv = 1.0f / s;
        #pragma unroll
        for (int j = 0; j < 8; j++) { x[j] *= inv; ksl[j] += x[j]; }

        ulonglong2* kd = (ulonglong2*)&k_dup[tok8][lane8 * 8];
        kd[0] = make_ulonglong2(dup2(x[0]), dup2(x[1]));
        kd[1] = make_ulonglong2(dup2(x[2]), dup2(x[3]));
        kd[2] = make_ulonglong2(dup2(x[4]), dup2(x[5]));
        kd[3] = make_ulonglong2(dup2(x[6]), dup2(x[7]));
        *(float4*)&v_sm[tok8][lane8 * 8]     = va4;
        *(float4*)&v_sm[tok8][lane8 * 8 + 4] = vb4;
        __syncthreads();

        // prefetch next tile (latency hidden under FMA loop)
        if (tile + 1 < NT1) {
            off += step;
            ka4 = *(const float4*)(keys + off);
            kb4 = *(const float4*)(keys + off + 4);
            va4 = *(const float4*)(values + off);
            vb4 = *(const float4*)(values + off + 4);
        }

        #pragma unroll 4
        for (int t = 0; t < TILE1; t++) {
            const ulonglong2 ka = *(const ulonglong2*)&k_dup[t][d0];
            const ulonglong2 kb = *(const ulonglong2*)&k_dup[t][d0 + 2];
            const ulonglong2 vv = *(const ulonglong2*)&v_sm[t][e0];
            FFMA2(acc[0][0], ka.x, vv.x, acc[0][0]);
            FFMA2(acc[0][1], ka.x, vv.y, acc[0][1]);
            FFMA2(acc[1][0], ka.y, vv.x, acc[1][0]);
            FFMA2(acc[1][1], ka.y, vv.y, acc[1][1]);
            FFMA2(acc[2][0], kb.x, vv.x, acc[2][0]);
            FFMA2(acc[2][1], kb.x, vv.y, acc[2][1]);
            FFMA2(acc[3][0], kb.y, vv.x, acc[3][0]);
            FFMA2(acc[3][1], kb.y, vv.y, acc[3][1]);
        }
        __syncthreads();
    }

    // block-reduce ksum
    #pragma unroll
    for (int j = 0; j < 8; j++) {
        float v = ksl[j];
        v += __shfl_xor_sync(0xffffffffu, v, 8);
        v += __shfl_xor_sync(0xffffffffu, v, 16);
        if ((tid & 24) == 0) atomicAdd(&ksum_sm[lane8 * 8 + j], v);
    }
    __syncthreads();
    if (tid < E) g_ksum_part[split][bh][tid] = ksum_sm[tid];

    float* kvp = g_kv_part[split][bh];
    #pragma unroll
    for (int i = 0; i < 4; i++) {
        ulonglong2 row = make_ulonglong2(acc[i][0], acc[i][1]);
        *(ulonglong2*)&kvp[(d0 + i) * E + e0] = row;
    }
}

// ---------------------------------------------------------------------------
// Phase 2: out = z_l * softmax(q) @ kv
// grid (BH, P2_SPLIT), 256 threads, dynamic smem (49408 B), 2 CTAs/SM.
// Tile = 128 tokens. Loader: tid>>1 -> token, tid&1 -> 32-elem half.
// GEMV: tg = tid>>3 -> 4 tokens, lane8 = tid&7 -> 8 d. q pre-scaled by z.
// ---------------------------------------------------------------------------
__global__ __launch_bounds__(256, 2)
void phase2_kernel(const float* __restrict__ queries,
                   const float* __restrict__ delta1,
                   float* __restrict__ out) {
    extern __shared__ __align__(16) char smem_raw[];
    float (*kv_sm)[E] = (float (*)[E])(smem_raw + SM_KV);
    float (*q_sm)[E]  = (float (*)[E])(smem_raw + SM_Q);
    float* ksum_sm    = (float*)(smem_raw + SM_KSUM);

    const int bh    = blockIdx.x;
    const int split = blockIdx.y;
    const int b = bh >> 4;
    const int h = bh & 15;
    const int tid = threadIdx.x;

    const float inv_temp = 1.0f / log1pf(__expf(delta1[0]));

    {   // kv = sum of 8 split partials; ksum likewise
        float4* dst = (float4*)&kv_sm[0][0];
        #pragma unroll
        for (int i = 0; i < E*E/4/256; i++) {
            int idx = tid + i * 256;
            float4 a4 = make_float4(0.f, 0.f, 0.f, 0.f);
            #pragma unroll
            for (int sp = 0; sp < P1_SPLIT; sp++) {
                float4 p = *(const float4*)&g_kv_part[sp][bh][idx * 4];
                a4.x += p.x; a4.y += p.y; a4.z += p.z; a4.w += p.w;
            }
            dst[idx] = a4;
        }
        if (tid < E) {
            float sv = 0.f;
            #pragma unroll
            for (int sp = 0; sp < P1_SPLIT; sp++) sv += g_ksum_part[sp][bh][tid];
            ksum_sm[tid] = sv;
        }
    }
    __syncthreads();

    const int l0 = split * P2_CHUNK;
    const int tt   = tid >> 1;      // loader token
    const int half = tid & 1;       // 32-elem half
    const int tg    = tid >> 3;     // GEMV token group (4 tokens)
    const int lane8 = tid & 7;
    const int d0 = lane8 * 8;

    for (int tile = 0; tile < P2_CHUNK / TILE2; tile++) {
        // ---- load + softmax(q), pre-scale by z, store to q_sm ----
        {
            const int l = l0 + tile * TILE2 + tt;
            const size_t qoff = ((size_t)(b * L + l) * H + h) * E + (size_t)(half * 32);
            float x[32];
            #pragma unroll
            for (int i = 0; i < 8; i++) {
                float4 q4 = *(const float4*)(queries + qoff + i * 4);
                x[i*4+0] = soft_logit_exp(q4.x, inv_temp);
                x[i*4+1] = soft_logit_exp(q4.y, inv_temp);
                x[i*4+2] = soft_logit_exp(q4.z, inv_temp);
                x[i*4+3] = soft_logit_exp(q4.w, inv_temp);
            }
            float s = 0.f;
            #pragma unroll
            for (int j = 0; j < 32; j++) s += x[j];
            s += __shfl_xor_sync(0xffffffffu, s, 1);
            const float inv = 1.0f / s;
            float zd = 0.f;
            #pragma unroll
            for (int j = 0; j < 32; j++) {
                x[j] *= inv;
                zd = fmaf(x[j], ksum_sm[half * 32 + j], zd);
            }
            zd += __shfl_xor_sync(0xffffffffu, zd, 1);
            const float z = 1.0f / (zd + EPSF);
            #pragma unroll
            for (int i = 0; i < 8; i++) {
                float4 o = make_float4(x[i*4+0]*z, x[i*4+1]*z, x[i*4+2]*z, x[i*4+3]*z);
                *(float4*)&q_sm[tt][half * 32 + i * 4] = o;
            }
        }
        __syncthreads();

        // ---- GEMV: 4 tokens x 8 d per thread (16 FFMA2 / 6 LDS-wf per e) ----
        ull acc[4][4];
        #pragma unroll
        for (int j = 0; j < 4; j++)
            #pragma unroll
            for (int p = 0; p < 4; p++) acc[j][p] = 0ull;

        const int tb = tg * 4;
        #pragma unroll 4
        for (int e = 0; e < E; e++) {
            const ulonglong2 kva = *(const ulonglong2*)&kv_sm[e][d0];
            const ulonglong2 kvb = *(const ulonglong2*)&kv_sm[e][d0 + 4];
            #pragma unroll
            for (int j = 0; j < 4; j++) {
                const ull qd = dup2(q_sm[tb + j][e]);
                FFMA2(acc[j][0], qd, kva.x, acc[j][0]);
                FFMA2(acc[j][1], qd, kva.y, acc[j][1]);
                FFMA2(acc[j][2], qd, kvb.x, acc[j][2]);
                FFMA2(acc[j][3], qd, kvb.y, acc[j][3]);
            }
        }

        // ---- store: 4 tokens x 8 contiguous d ----
        #pragma unroll
        for (int j = 0; j < 4; j++) {
            const int l = l0 + tile * TILE2 + tb + j;
            const size_t o = ((size_t)(b * L + l) * H + h) * E + (size_t)d0;
            *(float4*)(out + o)     = make_float4(lo_f(acc[j][0]), hi_f(acc[j][0]),
                                                  lo_f(acc[j][1]), hi_f(acc[j][1]));
            *(float4*)(out + o + 4) = make_float4(lo_f(acc[j][2]), hi_f(acc[j][2]),
                                                  lo_f(acc[j][3]), hi_f(acc[j][3]));
        }
        __syncthreads();   // q_sm rewritten next tile
    }
}

extern "C" void kernel_launch(void* const* d_in, const int* in_sizes, int n_in,
                              void* d_out, int out_size) {
    const float* queries = (const float*)d_in[0];
    const float* keys    = (const float*)d_in[1];
    const float* values  = (const float*)d_in[2];
    const float* delta1  = (const float*)d_in[3];
    float* out = (float*)d_out;

    (void)in_sizes; (void)n_in; (void)out_size;

    cudaFuncSetAttribute(phase2_kernel,
                         cudaFuncAttributeMaxDynamicSharedMemorySize, SM2_TOTAL);

    phase1_kernel<<<dim3(BH, P1_SPLIT), 256>>>(keys, values, delta1);
    phase2_kernel<<<dim3(BH, P2_SPLIT), 256, SM2_TOTAL>>>(queries, delta1, out);
}